// round 14
// baseline (speedup 1.0000x reference)
#include <cuda_runtime.h>
#include <math.h>
#include <stdint.h>

// Problem constants
#define BB 64
#define CC 16
#define FF 2048
#define JT 25            // stored joints per feature row
#define SPB 4            // series per block
#define NPARTS 6         // 24 joints / 4
#define NT 256           // 8 warps
#define RS 2056          // padded row stride (words)
#define WCAP 288         // per (series,window) key capacity (~6.2 sigma mid)

#define DATA_WORDS (SPB * RS)                 // 8224
#define CAND_OFF   DATA_WORDS                 // 8224  (12 arrays: (ts*3+v)*WCAP)
#define HIST_OFF   (CAND_OFF + 12 * WCAP)     // 11680
#define REC_OFF    (HIST_OFF + 8 * 128)       // 12704 (32 records x 12 words)
#define CNT_OFF    (REC_OFF + 32 * 12)        // 13088
#define OFF_OFF    (CNT_OFF + 256)            // 13344
#define QOUT_OFF   (OFF_OFF + 256)            // 13600
#define SMEM_WORDS (QOUT_OFF + 32)            // 13632
#define SMEM_BYTES (SMEM_WORDS * 4)           // 54528 -> 4 blocks/SM if regs<=64

// Packed f32x2 ops (sm_103a)
#define PACKF2(out, lo, hi) \
    asm("mov.b64 %0, {%1, %2};" : "=l"(out) : "f"(lo), "f"(hi))
#define UNPACKF2(lo, hi, in) \
    asm("mov.b64 {%0, %1}, %2;" : "=f"(lo), "=f"(hi) : "l"(in))
#define ADDF2(d, a, b) \
    asm("add.rn.f32x2 %0, %1, %2;" : "=l"(d) : "l"(a), "l"(b))
#define MULF2(d, a, b) \
    asm("mul.rn.f32x2 %0, %1, %2;" : "=l"(d) : "l"(a), "l"(b))
#define FMAF2(d, a, b, c) \
    asm("fma.rn.f32x2 %0, %1, %2, %3;" : "=l"(d) : "l"(a), "l"(b), "l"(c))

__device__ float g_stat2[BB * CC * 16 * 12];   // (b, c, s, j)
__device__ float g_weff[5 * 16 * 16 * 12];     // (cls, c, s, j)

__device__ __forceinline__ unsigned f2key(float x) {
    unsigned b = __float_as_uint(x);
    return b ^ ((unsigned)(((int)b) >> 31) | 0x80000000u);
}
__device__ __forceinline__ float key2f(unsigned k) {
    unsigned u = (k & 0x80000000u) ? (k & 0x7fffffffu) : ~k;
    return __uint_as_float(u);
}

// ---------------------------------------------------------------------------
// 128-bin histogram rank search (warp-uniform r). Returns bin; updates r to
// rank-within-bin; outputs bin count.
// ---------------------------------------------------------------------------
__device__ __forceinline__ int warp_find_bin128(const unsigned* hist, int lane,
                                                int& r, int& bincount) {
    const unsigned full = 0xffffffffu;
    unsigned c[4]; unsigned run = 0;
#pragma unroll
    for (int t = 0; t < 4; t++) { c[t] = hist[lane * 4 + t]; run += c[t]; }
    unsigned inc = run;
#pragma unroll
    for (int d = 1; d < 32; d <<= 1) {
        unsigned v = __shfl_up_sync(full, inc, d);
        if (lane >= d) inc += v;
    }
    unsigned acc = inc - run;
    int bin = -1, newr = 0; unsigned bc = 0;
#pragma unroll
    for (int t = 0; t < 4; t++) {
        if (bin < 0 && (int)acc <= r && r < (int)(acc + c[t])) {
            bin = lane * 4 + t; newr = r - (int)acc; bc = c[t];
        }
        acc += c[t];
    }
    unsigned m = __ballot_sync(full, bin >= 0);
    int srcl = __ffs(m) - 1;
    bin  = __shfl_sync(full, bin, srcl);
    newr = __shfl_sync(full, newr, srcl);
    bc   = __shfl_sync(full, bc, srcl);
    r = newr; bincount = (int)bc;
    return bin;
}

// ---------------------------------------------------------------------------
// Correctness fallback: exact rank-r key via bisection over the intact row.
// ---------------------------------------------------------------------------
__device__ unsigned generic_select_row(const unsigned* row, int lane, int r) {
    const unsigned full = 0xffffffffu;
    unsigned Klo = 0u, Khi = 0xffffffffu;
#pragma unroll 1
    while (Klo < Khi) {
        unsigned mid = Klo + ((Khi - Klo) >> 1);
        int cle = 0;
        for (int i = 0; i < 64; i++)
            cle += (f2key(__uint_as_float(row[i * 32 + lane])) <= mid);
#pragma unroll
        for (int d = 16; d; d >>= 1) cle += __shfl_xor_sync(full, cle, d);
        if (r < cle) Khi = mid; else Klo = mid + 1u;
    }
    return Klo;
}

// ---------------------------------------------------------------------------
// Kernel A: one block per (b,c,part). Mask-based single-scan pipeline with
// packed-f32x2 moments; scatter of pre-filtered keys; 7-bit radix selection.
// ---------------------------------------------------------------------------
__global__ __launch_bounds__(NT)
void stats_kernel(const float* __restrict__ features,
                  const float* __restrict__ W2, const float* __restrict__ Wl) {
    extern __shared__ unsigned sm[];
    const unsigned full = 0xffffffffu;

    const int blk  = blockIdx.x;
    const int bc   = blk / NPARTS;
    const int part = blk - bc * NPARTS;       // 0..5 -> joints part*4 .. +3
    const int tid  = threadIdx.x;
    const int w    = tid >> 5;
    const int lane = tid & 31;
    const int jj   = tid & 3;                 // joint within part
    const int f0   = tid >> 2;                // f base (0..63)

    const float* src = features + (size_t)bc * (FF * JT) + part * 4;
    float* smf = reinterpret_cast<float*>(sm);

    // window pivots (data ~N(0,1); smem bisection fallback covers the rest)
    const float P0 = -0.80f, P1 = -0.55f, P2 = -0.125f,
                P3 =  0.125f, P4 =  0.55f, P5 =  0.80f;

    // ---- phase 1: load + transpose + packed moments + counts + masks ----
    unsigned m0 = 0u, m1 = 0u, m2 = 0u;
    {
        unsigned long long ps1 = 0ull, ps2 = 0ull, ps3 = 0ull, ps4 = 0ull;
        float mn = INFINITY, mx = -INFINITY;
        int c0 = 0, c2 = 0, c4 = 0;           // counts below P0, P2, P4
#pragma unroll
        for (int k = 0; k < 32; k += 2) {
            int fa = f0 + 64 * k;
            int fb = fa + 64;
            float xa = __ldg(src + (size_t)fa * JT + jj);
            float xb = __ldg(src + (size_t)fb * JT + jj);
            smf[jj * RS + fa] = xa;
            smf[jj * RS + fb] = xb;
            unsigned long long p, pp;
            PACKF2(p, xa, xb);
            ADDF2(ps1, ps1, p);
            MULF2(pp, p, p);
            ADDF2(ps2, ps2, pp);
            FMAF2(ps3, pp, p, ps3);
            FMAF2(ps4, pp, pp, ps4);
            mn = fminf(mn, fminf(xa, xb));
            mx = fmaxf(mx, fmaxf(xa, xb));
            // element a -> bit k
            bool a0 = xa < P0, a1 = xa < P1, a2 = xa < P2,
                 a3 = xa < P3, a4 = xa < P4, a5 = xa < P5;
            c0 += a0; c2 += a2; c4 += a4;
            if (a1 && !a0) m0 |= 1u << k;
            if (a3 && !a2) m1 |= 1u << k;
            if (a5 && !a4) m2 |= 1u << k;
            // element b -> bit k+1
            bool b0 = xb < P0, b1 = xb < P1, b2 = xb < P2,
                 b3 = xb < P3, b4 = xb < P4, b5 = xb < P5;
            c0 += b0; c2 += b2; c4 += b4;
            if (b1 && !b0) m0 |= 1u << (k + 1);
            if (b3 && !b2) m1 |= 1u << (k + 1);
            if (b5 && !b4) m2 |= 1u << (k + 1);
        }
        float l1, h1, l2, h2, l3, h3, l4, h4;
        UNPACKF2(l1, h1, ps1); UNPACKF2(l2, h2, ps2);
        UNPACKF2(l3, h3, ps3); UNPACKF2(l4, h4, ps4);
        float s1 = l1 + h1, s2 = l2 + h2, s3 = l3 + h3, s4 = l4 + h4;

        int n0 = __popc(m0), n1 = __popc(m1), n2 = __popc(m2);
        // per-thread packed window counts (10-bit fields)
        sm[CNT_OFF + tid] = (unsigned)n0 | ((unsigned)n1 << 10)
                          | ((unsigned)n2 << 20);
        // reduce over the 8 lanes sharing jj (xor 4,8,16 preserves lane&3)
#pragma unroll
        for (int d = 4; d <= 16; d <<= 1) {
            s1 += __shfl_xor_sync(full, s1, d);
            s2 += __shfl_xor_sync(full, s2, d);
            s3 += __shfl_xor_sync(full, s3, d);
            s4 += __shfl_xor_sync(full, s4, d);
            mn = fminf(mn, __shfl_xor_sync(full, mn, d));
            mx = fmaxf(mx, __shfl_xor_sync(full, mx, d));
            c0 += __shfl_xor_sync(full, c0, d);
            c2 += __shfl_xor_sync(full, c2, d);
            c4 += __shfl_xor_sync(full, c4, d);
            n0 += __shfl_xor_sync(full, n0, d);
            n1 += __shfl_xor_sync(full, n1, d);
            n2 += __shfl_xor_sync(full, n2, d);
        }
        if (lane < 4) {     // lane == jj for these lanes
            unsigned* r = sm + REC_OFF + (w * 4 + lane) * 12;
            r[0] = __float_as_uint(s1); r[1] = __float_as_uint(s2);
            r[2] = __float_as_uint(s3); r[3] = __float_as_uint(s4);
            r[4] = __float_as_uint(mn); r[5] = __float_as_uint(mx);
            r[6] = (unsigned)c0; r[7] = (unsigned)c2; r[8] = (unsigned)c4;
            r[9] = (unsigned)n0; r[10] = (unsigned)n1; r[11] = (unsigned)n2;
        }
    }
    __syncthreads();

    // ---- phase 2a: packed per-series exclusive scan (warps 0..3) ----
    if (w < 4) {
        unsigned ca = sm[CNT_OFF + 8 * lane + w];
        unsigned cb = sm[CNT_OFF + 8 * lane + 4 + w];
        unsigned ps = ca + cb;
        unsigned inc = ps;
#pragma unroll
        for (int d = 1; d < 32; d <<= 1) {
            unsigned v = __shfl_up_sync(full, inc, d);
            if (lane >= d) inc += v;
        }
        unsigned ex = inc - ps;
        sm[OFF_OFF + 8 * lane + w] = ex;
        sm[OFF_OFF + 8 * lane + 4 + w] = ex + ca;
    }
    __syncthreads();

    // ---- phase 2b: scatter pre-converted keys, split per window ----
    {
        unsigned offp = sm[OFF_OFF + tid];
        int o0 = offp & 1023, o1 = (offp >> 10) & 1023, o2 = (offp >> 20) & 1023;
        unsigned* cbase = sm + CAND_OFF + jj * (3 * WCAP);
        unsigned mall = m0 | m1 | m2;
        while (mall) {
            int k = __ffs(mall) - 1; mall &= mall - 1;
            float x = smf[jj * RS + f0 + 64 * k];
            unsigned key = f2key(x);
            if ((m0 >> k) & 1) { if (o0 < WCAP) cbase[o0] = key; o0++; }
            else if ((m1 >> k) & 1) { if (o1 < WCAP) cbase[WCAP + o1] = key; o1++; }
            else { if (o2 < WCAP) cbase[2 * WCAP + o2] = key; o2++; }
        }
    }
    __syncthreads();

    // ---- phase 3: 12 selection tasks over 8 warps ----
    const int R0[3] = {511, 1023, 1535};
    unsigned* hist = sm + HIST_OFF + w * 128;
    float* qout = reinterpret_cast<float*>(sm + QOUT_OFF);

#pragma unroll 1
    for (int pass = 0; pass < 2; pass++) {
        int t = (pass == 0) ? w : (w < 4 ? 8 + w : -1);
        if (t < 0) break;
        int ts = t / 3, v = t - ts * 3;
        int need1 = (v != 1);

        // exact counts from records (lanes 0..7 hold warp-records of ts)
        int cl = 0, w0 = 0, w1 = 0, w2 = 0;
        if (lane < 8) {
            const unsigned* r = sm + REC_OFF + (lane * 4 + ts) * 12;
            cl = (int)r[6 + v];
            w0 = (int)r[9]; w1 = (int)r[10]; w2 = (int)r[11];
        }
#pragma unroll
        for (int d = 1; d <= 4; d <<= 1) {
            cl += __shfl_xor_sync(full, cl, d);
            w0 += __shfl_xor_sync(full, w0, d);
            w1 += __shfl_xor_sync(full, w1, d);
            w2 += __shfl_xor_sync(full, w2, d);
        }
        cl = __shfl_sync(full, cl, 0);
        w0 = __shfl_sync(full, w0, 0);
        w1 = __shfl_sync(full, w1, 0);
        w2 = __shfl_sync(full, w2, 0);
        int wc = (v == 0) ? w0 : (v == 1) ? w1 : w2;
        int wmax = max(w0, max(w1, w2));
        int lr = R0[v] - cl;

        // fast path valid: offsets exact (no 10-bit carry), capacity, bracket
        bool ok = (wmax <= 1023) && (wc <= WCAP) && (lr >= 0) &&
                  ((lr + need1) < wc);
        float v0, v1 = 0.f;
        if (ok) {
            const unsigned* cnd = sm + CAND_OFF + (ts * 3 + v) * WCAP;
            // minmax over the pre-filtered keys
            unsigned kmn = 0xffffffffu, kmx = 0u;
            for (int idx = lane; idx < wc; idx += 32) {
                unsigned k = cnd[idx];
                kmn = min(kmn, k); kmx = max(kmx, k);
            }
#pragma unroll
            for (int d = 16; d; d >>= 1) {
                kmn = min(kmn, __shfl_xor_sync(full, kmn, d));
                kmx = max(kmx, __shfl_xor_sync(full, kmx, d));
            }
            __syncwarp();

            unsigned k0, k1;
            if (kmn == kmx) {
                k0 = kmn; k1 = kmn;
            } else {
                // adaptive 7-bit radix rounds directly on cnd
                unsigned prefix = 0u, pmask = 0u;
                unsigned diff = kmn ^ kmx;
                int hib = 31 - __clz(diff);
                int sh = hib > 6 ? hib - 6 : 0;
                int cc = wc, lrr = lr;
#pragma unroll 1
                for (int round = 0; round < 6; round++) {
#pragma unroll
                    for (int u = 0; u < 4; u++) hist[lane + u * 32] = 0u;
                    __syncwarp();
                    for (int idx = lane; idx < wc; idx += 32) {
                        unsigned kk = cnd[idx];
                        if ((kk & pmask) == prefix)
                            atomicAdd(&hist[(kk >> sh) & 0x7Fu], 1u);
                    }
                    __syncwarp();
                    int bcnt;
                    int b = warp_find_bin128(hist, lane, lrr, bcnt);
                    prefix |= (unsigned)b << sh;
                    pmask  |= 0x7Fu << sh;
                    cc = bcnt;
                    __syncwarp();
                    if (cc <= 32 || sh == 0) break;
                    sh = (sh >= 7) ? sh - 7 : 0;
                }
                // final gather of matching keys (<=32, or all-identical)
                unsigned* s32 = hist;   // hist dead now
                unsigned mna = 0xffffffffu;
                int pos = 0;
                for (int base = 0; base < wc; base += 32) {
                    int idx = base + lane;
                    bool match = false; unsigned kk = 0u;
                    if (idx < wc) {
                        kk = cnd[idx];
                        unsigned masked = kk & pmask;
                        if (masked == prefix) match = true;
                        else if (masked > prefix) mna = min(mna, kk);
                    }
                    unsigned m = __ballot_sync(full, match);
                    if (match) {
                        int p2 = pos + __popc(m & ((1u << lane) - 1u));
                        if (p2 < 32) s32[p2] = kk;
                    }
                    pos += __popc(m);
                }
#pragma unroll
                for (int d = 16; d; d >>= 1)
                    mna = min(mna, __shfl_xor_sync(full, mna, d));
                __syncwarp();
                if (cc <= 32) {
                    unsigned vv = (lane < cc) ? s32[lane] : 0xffffffffu;
#pragma unroll
                    for (int k2 = 2; k2 <= 32; k2 <<= 1)
#pragma unroll
                        for (int j = k2 >> 1; j; j >>= 1) {
                            unsigned o = __shfl_xor_sync(full, vv, j);
                            bool keepMin = ((lane & j) == 0) == ((lane & k2) == 0);
                            vv = keepMin ? min(vv, o) : max(vv, o);
                        }
                    k0 = __shfl_sync(full, vv, lrr);
                    unsigned k1n = __shfl_sync(full, vv, (lrr + 1) & 31);
                    k1 = (lrr + 1 < cc) ? k1n : mna;
                } else {
                    // sh reached 0 with cc>32: all matching keys identical
                    k0 = s32[0];
                    k1 = (lrr + 1 < cc) ? k0 : mna;
                }
            }
            v0 = key2f(k0);
            if (need1) v1 = key2f(k1);
        } else {
            const unsigned* row = sm + ts * RS;
            v0 = key2f(generic_select_row(row, lane, R0[v]));
            if (need1) v1 = key2f(generic_select_row(row, lane, R0[v] + 1));
        }
        if (lane == 0) {
            float* qo = qout + ts * 8;
            if (v == 0) { qo[0] = v0; qo[1] = v1; }
            else if (v == 1) { qo[2] = v0; }
            else { qo[3] = v0; qo[4] = v1; }
        }
    }
    __syncthreads();

    // ---- phase 4: finalize (warp 0, lanes 0..3 -> one series each) ----
    if (w == 0 && lane < SPB) {
        int ts = lane;
        float ts1 = 0.f, ts2 = 0.f, ts3 = 0.f, ts4 = 0.f;
        float tmn = INFINITY, tmx = -INFINITY;
#pragma unroll
        for (int w2 = 0; w2 < 8; w2++) {
            const unsigned* r = sm + REC_OFF + (w2 * 4 + ts) * 12;
            ts1 += __uint_as_float(r[0]); ts2 += __uint_as_float(r[1]);
            ts3 += __uint_as_float(r[2]); ts4 += __uint_as_float(r[3]);
            tmn = fminf(tmn, __uint_as_float(r[4]));
            tmx = fmaxf(tmx, __uint_as_float(r[5]));
        }
        const float* qo = qout + ts * 8;
        const float n = 2048.f;
        float mean = ts1 / n;
        float m2 = ts2 / n, m3 = ts3 / n, m4 = ts4 / n;
        float varp = m2 - mean * mean;
        float var1 = varp * (n / (n - 1.f));
        float sd = sqrtf(var1);
        float mu2 = mean * mean;
        float m4c = m4 - 4.f * mean * m3 + 6.f * mu2 * m2 - 3.f * mu2 * mu2;
        float kurt = m4c / (var1 * var1) - 3.f;
        float q25 = 0.25f * qo[0] + 0.75f * qo[1];   // pos 511.75
        float med = qo[2];                            // pos 1023
        float q75 = 0.75f * qo[3] + 0.25f * qo[4];   // pos 1535.25

        int jg = part * SPB + ts;                     // 0..23
        int base = (jg < 12) ? 0 : 8;
        int col  = (jg < 12) ? jg : (jg - 12);
        float* o = g_stat2 + ((size_t)bc * 16 + base) * 12 + col;
        o[0 * 12] = tmx;
        o[1 * 12] = q25;
        o[2 * 12] = med;
        o[3 * 12] = q75;
        o[4 * 12] = mean;
        o[5 * 12] = sd;
        o[6 * 12] = tmx - tmn;
        o[7 * 12] = kurt;
    }

    // ---- weff tail folded in: blocks 0..119, threads 0..127 ----
    if (blk < 120 && tid < 128) {
        int idx = blk * 128 + tid;                    // 0 .. 15359
        int j   = idx % 12;
        int sx  = (idx / 12) & 15;
        int cx  = (idx / 192) & 15;
        int cls = idx / 3072;
        float a = 0.f;
#pragma unroll 8
        for (int e = 0; e < 64; e++)
            a += __ldg(&Wl[cls * 1024 + e * 16 + sx]) *
                 __ldg(&W2[(e * 16 + cx) * 12 + j]);
        g_weff[idx] = a;
    }
}

// ---------------------------------------------------------------------------
// Kernel B: logits[b,cls] = dot(stat2[b], weff[cls]) + sum b2*Wl + bl
// float4-vectorized: 14 wide loads per thread instead of 40 scalar.
// ---------------------------------------------------------------------------
__global__ __launch_bounds__(128)
void logits_kernel(const float* __restrict__ Wl, const float* __restrict__ b2,
                   const float* __restrict__ bl, float* __restrict__ out) {
    __shared__ float part[4];
    const unsigned full = 0xffffffffu;
    int blk = blockIdx.x;
    int b = blk / 5, cls = blk - b * 5;
    int tid = threadIdx.x;
    const float4* st4 = reinterpret_cast<const float4*>(g_stat2 + (size_t)b * 3072);
    const float4* wf4 = reinterpret_cast<const float4*>(g_weff + (size_t)cls * 3072);
    float a = 0.f;
#pragma unroll
    for (int i = tid; i < 768; i += 128) {
        float4 x = st4[i], y = wf4[i];
        a += x.x * y.x + x.y * y.y + x.z * y.z + x.w * y.w;
    }
    const float4* wl4 = reinterpret_cast<const float4*>(Wl + cls * 1024);
#pragma unroll
    for (int q = tid; q < 256; q += 128) {
        float4 v = __ldg(&wl4[q]);
        a += __ldg(&b2[q >> 2]) * (v.x + v.y + v.z + v.w);
    }
#pragma unroll
    for (int d = 16; d; d >>= 1) a += __shfl_xor_sync(full, a, d);
    if ((tid & 31) == 0) part[tid >> 5] = a;
    __syncthreads();
    if (tid == 0)
        out[b * 5 + cls] = part[0] + part[1] + part[2] + part[3] + bl[cls];
}

// ---------------------------------------------------------------------------
extern "C" void kernel_launch(void* const* d_in, const int* in_sizes, int n_in,
                              void* d_out, int out_size) {
    const float* features = (const float*)d_in[0];
    // d_in[1]=W1, d_in[2]=b1 : dead in the reference (result discarded)
    const float* W2 = (const float*)d_in[3];
    const float* b2 = (const float*)d_in[4];
    const float* Wl = (const float*)d_in[5];
    const float* bl = (const float*)d_in[6];
    float* out = (float*)d_out;

    cudaFuncSetAttribute(stats_kernel,
                         cudaFuncAttributeMaxDynamicSharedMemorySize,
                         SMEM_BYTES);

    stats_kernel<<<BB * CC * NPARTS, NT, SMEM_BYTES>>>(features, W2, Wl);
    logits_kernel<<<BB * 5, 128>>>(Wl, b2, bl, out);
}

// round 15
// speedup vs baseline: 1.0673x; 1.0673x over previous
#include <cuda_runtime.h>
#include <math.h>
#include <stdint.h>

// Problem constants
#define BB 64
#define CC 16
#define FF 2048
#define JT 25            // stored joints per feature row
#define SPB 4            // series per block
#define NPARTS 6         // 24 joints / 4
#define NT 256           // 8 warps
#define RS 2056          // padded row stride (words)
#define WCAP 288         // per (series,window) key capacity (~6.2 sigma mid)

#define DATA_WORDS (SPB * RS)                 // 8224
#define CAND_OFF   DATA_WORDS                 // 8224  (12 arrays: (ts*3+v)*WCAP)
#define HIST_OFF   (CAND_OFF + 12 * WCAP)     // 11680
#define REC_OFF    (HIST_OFF + 8 * 256)       // 13728 (32 records x 12 words)
#define CNT_OFF    (REC_OFF + 32 * 12)        // 14112
#define OFF_OFF    (CNT_OFF + 256)            // 14368
#define QOUT_OFF   (OFF_OFF + 256)            // 14624
#define SMEM_WORDS (QOUT_OFF + 32)            // 14656
#define SMEM_BYTES (SMEM_WORDS * 4)           // 58624 -> 3 blocks/SM

__device__ float g_stat2[BB * CC * 16 * 12];   // (b, c, s, j)
__device__ float g_weff[5 * 16 * 16 * 12];     // (cls, c, s, j)

__device__ __forceinline__ unsigned f2key(float x) {
    unsigned b = __float_as_uint(x);
    return b ^ ((unsigned)(((int)b) >> 31) | 0x80000000u);
}
__device__ __forceinline__ float key2f(unsigned k) {
    unsigned u = (k & 0x80000000u) ? (k & 0x7fffffffu) : ~k;
    return __uint_as_float(u);
}

// ---------------------------------------------------------------------------
// 256-bin histogram rank search (warp-uniform r). Returns bin; updates r to
// rank-within-bin; outputs bin count.
// ---------------------------------------------------------------------------
__device__ __forceinline__ int warp_find_bin256(const unsigned* hist, int lane,
                                                int& r, int& bincount) {
    const unsigned full = 0xffffffffu;
    unsigned c[8]; unsigned run = 0;
#pragma unroll
    for (int t = 0; t < 8; t++) { c[t] = hist[lane * 8 + t]; run += c[t]; }
    unsigned inc = run;
#pragma unroll
    for (int d = 1; d < 32; d <<= 1) {
        unsigned v = __shfl_up_sync(full, inc, d);
        if (lane >= d) inc += v;
    }
    unsigned acc = inc - run;
    int bin = -1, newr = 0; unsigned bc = 0;
#pragma unroll
    for (int t = 0; t < 8; t++) {
        if (bin < 0 && (int)acc <= r && r < (int)(acc + c[t])) {
            bin = lane * 8 + t; newr = r - (int)acc; bc = c[t];
        }
        acc += c[t];
    }
    unsigned m = __ballot_sync(full, bin >= 0);
    int srcl = __ffs(m) - 1;
    bin  = __shfl_sync(full, bin, srcl);
    newr = __shfl_sync(full, newr, srcl);
    bc   = __shfl_sync(full, bc, srcl);
    r = newr; bincount = (int)bc;
    return bin;
}

// ---------------------------------------------------------------------------
// Correctness fallback: exact rank-r key via bisection over the intact row.
// ---------------------------------------------------------------------------
__device__ unsigned generic_select_row(const unsigned* row, int lane, int r) {
    const unsigned full = 0xffffffffu;
    unsigned Klo = 0u, Khi = 0xffffffffu;
#pragma unroll 1
    while (Klo < Khi) {
        unsigned mid = Klo + ((Khi - Klo) >> 1);
        int cle = 0;
        for (int i = 0; i < 64; i++)
            cle += (f2key(__uint_as_float(row[i * 32 + lane])) <= mid);
#pragma unroll
        for (int d = 16; d; d >>= 1) cle += __shfl_xor_sync(full, cle, d);
        if (r < cle) Khi = mid; else Klo = mid + 1u;
    }
    return Klo;
}

// ---------------------------------------------------------------------------
// Kernel A: one block per (b,c,part). Mask-based single-scan pipeline:
// phase 1 = load+moments+masks; phase 2 = packed scan + direct scatter of
// pre-filtered KEYS per (series,window); phase 3 = selection (no pass A).
// (R13 winner, unmodified.)
// ---------------------------------------------------------------------------
__global__ __launch_bounds__(NT)
void stats_kernel(const float* __restrict__ features,
                  const float* __restrict__ W2, const float* __restrict__ Wl) {
    extern __shared__ unsigned sm[];
    const unsigned full = 0xffffffffu;

    const int blk  = blockIdx.x;
    const int bc   = blk / NPARTS;
    const int part = blk - bc * NPARTS;       // 0..5 -> joints part*4 .. +3
    const int tid  = threadIdx.x;
    const int w    = tid >> 5;
    const int lane = tid & 31;
    const int jj   = tid & 3;                 // joint within part
    const int f0   = tid >> 2;                // f base (0..63)

    const float* src = features + (size_t)bc * (FF * JT) + part * 4;
    float* smf = reinterpret_cast<float*>(sm);

    // window pivots (data ~N(0,1); smem bisection fallback covers the rest)
    const float P0 = -0.80f, P1 = -0.55f, P2 = -0.125f,
                P3 =  0.125f, P4 =  0.55f, P5 =  0.80f;

    // ---- phase 1: load + transpose + moments + counts + window masks ----
    unsigned m0 = 0u, m1 = 0u, m2 = 0u;
    {
        float s1 = 0.f, s2 = 0.f, s3 = 0.f, s4 = 0.f;
        float mn = INFINITY, mx = -INFINITY;
        int c0 = 0, c2 = 0, c4 = 0;           // counts below P0, P2, P4
#pragma unroll 8
        for (int k = 0; k < 32; k++) {
            int f = f0 + 64 * k;
            float x = __ldg(src + (size_t)f * JT + jj);
            smf[jj * RS + f] = x;
            s1 += x;
            float x2 = x * x;
            s2 += x2; s3 += x2 * x; s4 += x2 * x2;
            mn = fminf(mn, x); mx = fmaxf(mx, x);
            bool b0 = x < P0, b1 = x < P1, b2 = x < P2,
                 b3 = x < P3, b4 = x < P4, b5 = x < P5;
            c0 += b0; c2 += b2; c4 += b4;
            if (b1 && !b0) m0 |= 1u << k;
            if (b3 && !b2) m1 |= 1u << k;
            if (b5 && !b4) m2 |= 1u << k;
        }
        int n0 = __popc(m0), n1 = __popc(m1), n2 = __popc(m2);
        // per-thread packed window counts (10-bit fields)
        sm[CNT_OFF + tid] = (unsigned)n0 | ((unsigned)n1 << 10)
                          | ((unsigned)n2 << 20);
        // reduce over the 8 lanes sharing jj (xor 4,8,16 preserves lane&3)
#pragma unroll
        for (int d = 4; d <= 16; d <<= 1) {
            s1 += __shfl_xor_sync(full, s1, d);
            s2 += __shfl_xor_sync(full, s2, d);
            s3 += __shfl_xor_sync(full, s3, d);
            s4 += __shfl_xor_sync(full, s4, d);
            mn = fminf(mn, __shfl_xor_sync(full, mn, d));
            mx = fmaxf(mx, __shfl_xor_sync(full, mx, d));
            c0 += __shfl_xor_sync(full, c0, d);
            c2 += __shfl_xor_sync(full, c2, d);
            c4 += __shfl_xor_sync(full, c4, d);
            n0 += __shfl_xor_sync(full, n0, d);
            n1 += __shfl_xor_sync(full, n1, d);
            n2 += __shfl_xor_sync(full, n2, d);
        }
        if (lane < 4) {     // lane == jj for these lanes
            unsigned* r = sm + REC_OFF + (w * 4 + lane) * 12;
            r[0] = __float_as_uint(s1); r[1] = __float_as_uint(s2);
            r[2] = __float_as_uint(s3); r[3] = __float_as_uint(s4);
            r[4] = __float_as_uint(mn); r[5] = __float_as_uint(mx);
            r[6] = (unsigned)c0; r[7] = (unsigned)c2; r[8] = (unsigned)c4;
            r[9] = (unsigned)n0; r[10] = (unsigned)n1; r[11] = (unsigned)n2;
        }
    }
    __syncthreads();

    // ---- phase 2a: packed per-series exclusive scan (warps 0..3) ----
    if (w < 4) {
        unsigned ca = sm[CNT_OFF + 8 * lane + w];
        unsigned cb = sm[CNT_OFF + 8 * lane + 4 + w];
        unsigned ps = ca + cb;
        unsigned inc = ps;
#pragma unroll
        for (int d = 1; d < 32; d <<= 1) {
            unsigned v = __shfl_up_sync(full, inc, d);
            if (lane >= d) inc += v;
        }
        unsigned ex = inc - ps;
        sm[OFF_OFF + 8 * lane + w] = ex;
        sm[OFF_OFF + 8 * lane + 4 + w] = ex + ca;
    }
    __syncthreads();

    // ---- phase 2b: scatter pre-converted keys, split per window ----
    {
        unsigned offp = sm[OFF_OFF + tid];
        int o0 = offp & 1023, o1 = (offp >> 10) & 1023, o2 = (offp >> 20) & 1023;
        unsigned* cbase = sm + CAND_OFF + jj * (3 * WCAP);
        unsigned mall = m0 | m1 | m2;
        while (mall) {
            int k = __ffs(mall) - 1; mall &= mall - 1;
            float x = smf[jj * RS + f0 + 64 * k];
            unsigned key = f2key(x);
            if ((m0 >> k) & 1) { if (o0 < WCAP) cbase[o0] = key; o0++; }
            else if ((m1 >> k) & 1) { if (o1 < WCAP) cbase[WCAP + o1] = key; o1++; }
            else { if (o2 < WCAP) cbase[2 * WCAP + o2] = key; o2++; }
        }
    }
    __syncthreads();

    // ---- phase 3: 12 selection tasks over 8 warps ----
    const int R0[3] = {511, 1023, 1535};
    unsigned* hist = sm + HIST_OFF + w * 256;
    float* qout = reinterpret_cast<float*>(sm + QOUT_OFF);

#pragma unroll 1
    for (int pass = 0; pass < 2; pass++) {
        int t = (pass == 0) ? w : (w < 4 ? 8 + w : -1);
        if (t < 0) break;
        int ts = t / 3, v = t - ts * 3;
        int need1 = (v != 1);

        // exact counts from records (lanes 0..7 hold warp-records of ts)
        int cl = 0, w0 = 0, w1 = 0, w2 = 0;
        if (lane < 8) {
            const unsigned* r = sm + REC_OFF + (lane * 4 + ts) * 12;
            cl = (int)r[6 + v];
            w0 = (int)r[9]; w1 = (int)r[10]; w2 = (int)r[11];
        }
#pragma unroll
        for (int d = 1; d <= 4; d <<= 1) {
            cl += __shfl_xor_sync(full, cl, d);
            w0 += __shfl_xor_sync(full, w0, d);
            w1 += __shfl_xor_sync(full, w1, d);
            w2 += __shfl_xor_sync(full, w2, d);
        }
        cl = __shfl_sync(full, cl, 0);
        w0 = __shfl_sync(full, w0, 0);
        w1 = __shfl_sync(full, w1, 0);
        w2 = __shfl_sync(full, w2, 0);
        int wc = (v == 0) ? w0 : (v == 1) ? w1 : w2;
        int wmax = max(w0, max(w1, w2));
        int lr = R0[v] - cl;

        // fast path valid: offsets exact (no 10-bit carry), capacity, bracket
        bool ok = (wmax <= 1023) && (wc <= WCAP) && (lr >= 0) &&
                  ((lr + need1) < wc);
        float v0, v1 = 0.f;
        if (ok) {
            const unsigned* cnd = sm + CAND_OFF + (ts * 3 + v) * WCAP;
            // minmax over the pre-filtered keys
            unsigned kmn = 0xffffffffu, kmx = 0u;
            for (int idx = lane; idx < wc; idx += 32) {
                unsigned k = cnd[idx];
                kmn = min(kmn, k); kmx = max(kmx, k);
            }
#pragma unroll
            for (int d = 16; d; d >>= 1) {
                kmn = min(kmn, __shfl_xor_sync(full, kmn, d));
                kmx = max(kmx, __shfl_xor_sync(full, kmx, d));
            }
            __syncwarp();

            unsigned k0, k1;
            if (kmn == kmx) {
                k0 = kmn; k1 = kmn;
            } else {
                // adaptive 8-bit radix rounds directly on cnd
                unsigned prefix = 0u, pmask = 0u;
                unsigned diff = kmn ^ kmx;
                int hib = 31 - __clz(diff);
                int sh = hib > 7 ? hib - 7 : 0;
                int cc = wc, lrr = lr;
#pragma unroll 1
                for (int round = 0; round < 5; round++) {
#pragma unroll
                    for (int u = 0; u < 8; u++) hist[lane + u * 32] = 0u;
                    __syncwarp();
                    for (int idx = lane; idx < wc; idx += 32) {
                        unsigned kk = cnd[idx];
                        if ((kk & pmask) == prefix)
                            atomicAdd(&hist[(kk >> sh) & 0xFFu], 1u);
                    }
                    __syncwarp();
                    int bcnt;
                    int b = warp_find_bin256(hist, lane, lrr, bcnt);
                    prefix |= (unsigned)b << sh;
                    pmask  |= 0xFFu << sh;
                    cc = bcnt;
                    __syncwarp();
                    if (cc <= 32 || sh == 0) break;
                    sh = (sh >= 8) ? sh - 8 : 0;
                }
                // final gather of matching keys (<=32, or all-identical)
                unsigned* s32 = hist;   // hist dead now
                unsigned mna = 0xffffffffu;
                int pos = 0;
                for (int base = 0; base < wc; base += 32) {
                    int idx = base + lane;
                    bool match = false; unsigned kk = 0u;
                    if (idx < wc) {
                        kk = cnd[idx];
                        unsigned masked = kk & pmask;
                        if (masked == prefix) match = true;
                        else if (masked > prefix) mna = min(mna, kk);
                    }
                    unsigned m = __ballot_sync(full, match);
                    if (match) {
                        int p2 = pos + __popc(m & ((1u << lane) - 1u));
                        if (p2 < 32) s32[p2] = kk;
                    }
                    pos += __popc(m);
                }
#pragma unroll
                for (int d = 16; d; d >>= 1)
                    mna = min(mna, __shfl_xor_sync(full, mna, d));
                __syncwarp();
                if (cc <= 32) {
                    unsigned vv = (lane < cc) ? s32[lane] : 0xffffffffu;
#pragma unroll
                    for (int k2 = 2; k2 <= 32; k2 <<= 1)
#pragma unroll
                        for (int j = k2 >> 1; j; j >>= 1) {
                            unsigned o = __shfl_xor_sync(full, vv, j);
                            bool keepMin = ((lane & j) == 0) == ((lane & k2) == 0);
                            vv = keepMin ? min(vv, o) : max(vv, o);
                        }
                    k0 = __shfl_sync(full, vv, lrr);
                    unsigned k1n = __shfl_sync(full, vv, (lrr + 1) & 31);
                    k1 = (lrr + 1 < cc) ? k1n : mna;
                } else {
                    // sh reached 0 with cc>32: all matching keys identical
                    k0 = s32[0];
                    k1 = (lrr + 1 < cc) ? k0 : mna;
                }
            }
            v0 = key2f(k0);
            if (need1) v1 = key2f(k1);
        } else {
            const unsigned* row = sm + ts * RS;
            v0 = key2f(generic_select_row(row, lane, R0[v]));
            if (need1) v1 = key2f(generic_select_row(row, lane, R0[v] + 1));
        }
        if (lane == 0) {
            float* qo = qout + ts * 8;
            if (v == 0) { qo[0] = v0; qo[1] = v1; }
            else if (v == 1) { qo[2] = v0; }
            else { qo[3] = v0; qo[4] = v1; }
        }
    }
    __syncthreads();

    // ---- phase 4: finalize (warp 0, lanes 0..3 -> one series each) ----
    if (w == 0 && lane < SPB) {
        int ts = lane;
        float ts1 = 0.f, ts2 = 0.f, ts3 = 0.f, ts4 = 0.f;
        float tmn = INFINITY, tmx = -INFINITY;
#pragma unroll
        for (int w2 = 0; w2 < 8; w2++) {
            const unsigned* r = sm + REC_OFF + (w2 * 4 + ts) * 12;
            ts1 += __uint_as_float(r[0]); ts2 += __uint_as_float(r[1]);
            ts3 += __uint_as_float(r[2]); ts4 += __uint_as_float(r[3]);
            tmn = fminf(tmn, __uint_as_float(r[4]));
            tmx = fmaxf(tmx, __uint_as_float(r[5]));
        }
        const float* qo = qout + ts * 8;
        const float n = 2048.f;
        float mean = ts1 / n;
        float m2 = ts2 / n, m3 = ts3 / n, m4 = ts4 / n;
        float varp = m2 - mean * mean;
        float var1 = varp * (n / (n - 1.f));
        float sd = sqrtf(var1);
        float mu2 = mean * mean;
        float m4c = m4 - 4.f * mean * m3 + 6.f * mu2 * m2 - 3.f * mu2 * mu2;
        float kurt = m4c / (var1 * var1) - 3.f;
        float q25 = 0.25f * qo[0] + 0.75f * qo[1];   // pos 511.75
        float med = qo[2];                            // pos 1023
        float q75 = 0.75f * qo[3] + 0.25f * qo[4];   // pos 1535.25

        int jg = part * SPB + ts;                     // 0..23
        int base = (jg < 12) ? 0 : 8;
        int col  = (jg < 12) ? jg : (jg - 12);
        float* o = g_stat2 + ((size_t)bc * 16 + base) * 12 + col;
        o[0 * 12] = tmx;
        o[1 * 12] = q25;
        o[2 * 12] = med;
        o[3 * 12] = q75;
        o[4 * 12] = mean;
        o[5 * 12] = sd;
        o[6 * 12] = tmx - tmn;
        o[7 * 12] = kurt;
    }

    // ---- weff tail folded in: blocks 0..119, threads 0..127 ----
    if (blk < 120 && tid < 128) {
        int idx = blk * 128 + tid;                    // 0 .. 15359
        int j   = idx % 12;
        int sx  = (idx / 12) & 15;
        int cx  = (idx / 192) & 15;
        int cls = idx / 3072;
        float a = 0.f;
#pragma unroll 8
        for (int e = 0; e < 64; e++)
            a += __ldg(&Wl[cls * 1024 + e * 16 + sx]) *
                 __ldg(&W2[(e * 16 + cx) * 12 + j]);
        g_weff[idx] = a;
    }
}

// ---------------------------------------------------------------------------
// Kernel B: logits[b,cls] = dot(stat2[b], weff[cls]) + sum b2*Wl + bl
// float4-vectorized (R14, proven 5.8us).
// ---------------------------------------------------------------------------
__global__ __launch_bounds__(128)
void logits_kernel(const float* __restrict__ Wl, const float* __restrict__ b2,
                   const float* __restrict__ bl, float* __restrict__ out) {
    __shared__ float part[4];
    const unsigned full = 0xffffffffu;
    int blk = blockIdx.x;
    int b = blk / 5, cls = blk - b * 5;
    int tid = threadIdx.x;
    const float4* st4 = reinterpret_cast<const float4*>(g_stat2 + (size_t)b * 3072);
    const float4* wf4 = reinterpret_cast<const float4*>(g_weff + (size_t)cls * 3072);
    float a = 0.f;
#pragma unroll
    for (int i = tid; i < 768; i += 128) {
        float4 x = st4[i], y = wf4[i];
        a += x.x * y.x + x.y * y.y + x.z * y.z + x.w * y.w;
    }
    const float4* wl4 = reinterpret_cast<const float4*>(Wl + cls * 1024);
#pragma unroll
    for (int q = tid; q < 256; q += 128) {
        float4 v = __ldg(&wl4[q]);
        a += __ldg(&b2[q >> 2]) * (v.x + v.y + v.z + v.w);
    }
#pragma unroll
    for (int d = 16; d; d >>= 1) a += __shfl_xor_sync(full, a, d);
    if ((tid & 31) == 0) part[tid >> 5] = a;
    __syncthreads();
    if (tid == 0)
        out[b * 5 + cls] = part[0] + part[1] + part[2] + part[3] + bl[cls];
}

// ---------------------------------------------------------------------------
extern "C" void kernel_launch(void* const* d_in, const int* in_sizes, int n_in,
                              void* d_out, int out_size) {
    const float* features = (const float*)d_in[0];
    // d_in[1]=W1, d_in[2]=b1 : dead in the reference (result discarded)
    const float* W2 = (const float*)d_in[3];
    const float* b2 = (const float*)d_in[4];
    const float* Wl = (const float*)d_in[5];
    const float* bl = (const float*)d_in[6];
    float* out = (float*)d_out;

    cudaFuncSetAttribute(stats_kernel,
                         cudaFuncAttributeMaxDynamicSharedMemorySize,
                         SMEM_BYTES);

    stats_kernel<<<BB * CC * NPARTS, NT, SMEM_BYTES>>>(features, W2, Wl);
    logits_kernel<<<BB * 5, 128>>>(Wl, b2, bl, out);
}